// round 14
// baseline (speedup 1.0000x reference)
#include <cuda_runtime.h>
#include <cuda_bf16.h>

// BoxDecoder: anchor decode + score-threshold mask.
// out layout (f32): [ box_tensor (B*A*C*6) | mask (B*A*C) | batch_index (B*A*C) ]
//
// R14 = R13 (mask fused from registers; no cls re-read) + mask stores routed
// through a second smem staging buffer so they are fully coalesced (R13's
// 32B-lane-stride mask STGs doubled store wavefronts).
//  * box: quarter-buffer staging, ROW=52 (float4-aligned, 52*4 mod 128
//    pattern conflict-free for STS.128), flush 3 f4/thread/round.
//  * mask: MROW=12 (8 data + 4 pad; 12*l mod 32 distinct -> conflict-free
//    STS.128), flush 64 contiguous f4/round by tid<64.
//  * division elimination; decode loads issued first; plain default-policy
//    loads/stores (all alternatives measured neutral/worse; kernel pinned at
//    HBM mixed R/W ceiling ~5.9 TB/s, 74% DRAM).

constexpr int TPB    = 128;       // 4 warps per block
constexpr int STAGE  = 32;        // t's staged per round
constexpr int ROUNDS = TPB / STAGE;
constexpr int ROW    = 52;        // box smem row stride (48 data + 4 pad)
constexpr int MROW   = 12;        // mask smem row stride (8 data + 4 pad)

__global__ void __launch_bounds__(TPB)
box_decode_c8_kernel(const float* __restrict__ anchors,   // [A,4] cx,cy,w,h
                     const float* __restrict__ loc,       // [B,A,4]
                     const float* __restrict__ cls,       // [B,A,8]
                     const float* __restrict__ varx_p,
                     const float* __restrict__ vary_p,
                     const float* __restrict__ thr_p,
                     float* __restrict__ out_box,         // [B*A*8, 6]
                     float* __restrict__ out_mask,        // [B*A*8] or null
                     float* __restrict__ out_bidx,        // [B*A*8] or null
                     int A, long long total)              // total = B*A
{
    __shared__ float sm [STAGE * ROW];                    // box stage (6.65KB)
    __shared__ float smm[STAGE * MROW];                   // mask stage (1.5KB)

    const long long bs = (long long)blockIdx.x * TPB;   // first t of this block
    const int tid = threadIdx.x;
    const long long t = bs + tid;

    const float varx = *varx_p;
    const float vary = *vary_p;
    const float thr  = *thr_p;

    // One divide per thread; batch id via boundary compare (A >> TPB).
    const int b0   = (int)(bs / A);
    const int rem0 = (int)(bs - (long long)b0 * A);     // anchor idx of t = bs

    // ---- decode own t into registers (long-pole loads issue early) ----
    float x0 = 0.f, y0 = 0.f, x1 = 0.f, y1 = 0.f;
    float s[8] = {0.f, 0.f, 0.f, 0.f, 0.f, 0.f, 0.f, 0.f};
    if (t < total) {
        int a = rem0 + tid;
        if (a >= A) a -= A;                         // at most one boundary per block

        float4 anc = __ldg((const float4*)anchors + a);   // cx,cy,w,h (L2-reused)
        float4 lp  = __ldg((const float4*)loc + t);

        float4 s01 = __ldg((const float4*)cls + t * 2);
        float4 s23 = __ldg((const float4*)cls + t * 2 + 1);

        float cx = lp.x * varx * anc.z + anc.x;
        float cy = lp.y * varx * anc.w + anc.y;
        float wd = __expf(lp.z * vary) * anc.z;
        float ht = __expf(lp.w * vary) * anc.w;

        x0 = cx - 0.5f * wd;
        y0 = cy - 0.5f * ht;
        x1 = cx + 0.5f * wd;
        y1 = cy + 0.5f * ht;

        s[0] = s01.x; s[1] = s01.y; s[2] = s01.z; s[3] = s01.w;
        s[4] = s23.x; s[5] = s23.y; s[6] = s23.z; s[7] = s23.w;
    }

    // ---- batch_index: derived from index, coalesced ----
    if (out_bidx) {
#pragma unroll
        for (int k = 0; k < 2; k++) {
            long long j = bs * 2 + (long long)k * TPB + tid;  // float4 idx, t' = j>>1
            if (j < total * 2) {
                int off = rem0 + k * (TPB / 2) + (tid >> 1);  // t' - b0*A
                float bf = (float)(b0 + (off >= A ? 1 : 0));
                ((float4*)out_bidx)[j] = make_float4(bf, bf, bf, bf);
            }
        }
    }

    // ---- ROUNDS rounds: stage STAGE t's (box + mask), flush coalesced ----
#pragma unroll
    for (int round = 0; round < ROUNDS; round++) {
        if ((tid >> 5) == round && t < total) {
            const int sl = tid & (STAGE - 1);
            float4* row = (float4*)(sm + sl * ROW);
#pragma unroll
            for (int p = 0; p < 4; p++) {          // class pair (2p, 2p+1)
                row[3 * p + 0] = make_float4(x0, y0, x1, y1);
                row[3 * p + 1] = make_float4(s[2 * p], (float)(2 * p + 1), x0, y0);
                row[3 * p + 2] = make_float4(x1, y1, s[2 * p + 1], (float)(2 * p + 2));
            }
            if (out_mask) {
                float4* mrow = (float4*)(smm + sl * MROW);
                mrow[0] = make_float4(s[0] >= thr ? 1.0f : 0.0f,
                                      s[1] >= thr ? 1.0f : 0.0f,
                                      s[2] >= thr ? 1.0f : 0.0f,
                                      s[3] >= thr ? 1.0f : 0.0f);
                mrow[1] = make_float4(s[4] >= thr ? 1.0f : 0.0f,
                                      s[5] >= thr ? 1.0f : 0.0f,
                                      s[6] >= thr ? 1.0f : 0.0f,
                                      s[7] >= thr ? 1.0f : 0.0f);
            }
        }
        __syncthreads();

        const long long rbase = bs + (long long)round * STAGE;    // first t this round
        const int nvalid = (int)max(0LL, min((long long)STAGE, total - rbase));

        // box flush: 384 f4 / 128 threads = 3 each, contiguous gmem
        {
            const int nf4 = nvalid * 12;
            float4* dst = (float4*)out_box + rbase * 12;
#pragma unroll
            for (int k = 0; k < 3; k++) {          // STAGE*12 / TPB = 3
                int i = tid + k * TPB;
                if (i < nf4) {
                    int tl  = i / 12;              // div by constant: mul+shift
                    int pos = i - tl * 12;
                    dst[i] = *(const float4*)(sm + tl * ROW + pos * 4);
                }
            }
        }

        // mask flush: 64 f4, contiguous gmem, by tid < 64
        if (out_mask && tid < 2 * STAGE) {
            const int i = tid;                     // 0..63
            if (i < nvalid * 2) {
                int tl  = i >> 1;
                int pos = i & 1;
                ((float4*)out_mask)[rbase * 2 + i] =
                    *(const float4*)(smm + tl * MROW + pos * 4);
            }
        }

        if (round != ROUNDS - 1) __syncthreads();  // protect buffers before reuse
    }
}

// Generic-C fallback (scalar stores), in case C != 8.
__global__ void __launch_bounds__(256)
box_decode_generic_kernel(const float* __restrict__ anchors,
                          const float* __restrict__ loc,
                          const float* __restrict__ cls,
                          const float* __restrict__ varx_p,
                          const float* __restrict__ vary_p,
                          const float* __restrict__ thr_p,
                          float* __restrict__ out_box,
                          float* __restrict__ out_mask,
                          float* __restrict__ out_bidx,
                          int A, int C, long long total)
{
    long long t = (long long)blockIdx.x * blockDim.x + threadIdx.x;
    if (t >= total) return;

    const float varx = *varx_p;
    const float vary = *vary_p;
    const float thr  = *thr_p;

    int b = (int)(t / A);
    int a = (int)(t - (long long)b * A);

    float4 anc = __ldg((const float4*)anchors + a);
    float4 lp  = __ldg((const float4*)loc + t);

    float cx = lp.x * varx * anc.z + anc.x;
    float cy = lp.y * varx * anc.w + anc.y;
    float w  = expf(lp.z * vary) * anc.z;
    float h  = expf(lp.w * vary) * anc.w;

    float x0 = cx - 0.5f * w;
    float y0 = cy - 0.5f * h;
    float x1 = cx + 0.5f * w;
    float y1 = cy + 0.5f * h;

    for (int c = 0; c < C; c++) {
        long long r = t * C + c;
        float sc = cls[r];
        float* row = out_box + r * 6;
        row[0] = x0; row[1] = y0; row[2] = x1; row[3] = y1;
        row[4] = sc; row[5] = (float)(c + 1);
        if (out_mask) out_mask[r] = (sc >= thr) ? 1.0f : 0.0f;
        if (out_bidx) out_bidx[r] = (float)b;
    }
}

extern "C" void kernel_launch(void* const* d_in, const int* in_sizes, int n_in,
                              void* d_out, int out_size)
{
    // Input order per setup_inputs: anchors, loc_preds, cls_preds,
    // varx, vary, score_thresh, batch_size
    const float* anchors = (const float*)d_in[0];
    const float* loc     = (const float*)d_in[1];
    const float* cls     = (const float*)d_in[2];
    const float* varx_p  = (const float*)d_in[3];
    const float* vary_p  = (const float*)d_in[4];
    const float* thr_p   = (const float*)d_in[5];

    const long long A   = in_sizes[0] / 4;
    const long long B   = in_sizes[1] / (A * 4);
    const long long C   = in_sizes[2] / (B * A);
    const long long BAC = B * A * C;
    const long long total = B * A;

    float* out = (float*)d_out;
    float* out_box  = out;                                        // BAC*6
    float* out_mask = (out_size >= (long long)(BAC * 7)) ? out + BAC * 6 : nullptr;
    float* out_bidx = (out_size >= (long long)(BAC * 8)) ? out + BAC * 7 : nullptr;

    // Hedge: if the harness allocated more than we write, clear the tail
    // (d_out is poisoned to 0xAA). Graph-capturable async memset.
    long long written = BAC * 6;
    if (out_mask) written = BAC * 7;
    if (out_bidx) written = BAC * 8;
    if ((long long)out_size > written) {
        cudaMemsetAsync(out + written, 0,
                        ((long long)out_size - written) * sizeof(float));
    }

    if (C == 8) {
        const long long blocks = (total + TPB - 1) / TPB;
        box_decode_c8_kernel<<<(unsigned)blocks, TPB>>>(
            anchors, loc, cls, varx_p, vary_p, thr_p,
            out_box, out_mask, out_bidx, (int)A, total);
    } else {
        const int threads = 256;
        const long long blocks = (total + threads - 1) / threads;
        box_decode_generic_kernel<<<(unsigned)blocks, threads>>>(
            anchors, loc, cls, varx_p, vary_p, thr_p,
            out_box, out_mask, out_bidx, (int)A, (int)C, total);
    }
}

// round 15
// speedup vs baseline: 1.1899x; 1.1899x over previous
#include <cuda_runtime.h>
#include <cuda_bf16.h>

// BoxDecoder: anchor decode + score-threshold mask.
// out layout (f32): [ box_tensor (B*A*C*6) | mask (B*A*C) | batch_index (B*A*C) ]
//
// FINAL (== R13, the measured optimum: 72.96us kernel, 74.5% DRAM, 5.91TB/s):
//  * quarter-buffer block-phased smem staging: ROW=52 (float4-aligned,
//    conflict-free STS.128), 4 rounds of 32 t's, box flush 3 f4/thread/round,
//    all box stores perfectly coalesced.
//  * mask FUSED into decode (scores already in registers -> no 51MB cls
//    re-read); mask stores direct (32B lane stride — cheaper than staging,
//    R14 proved the smem-coalesced variant regresses).
//  * batch_index derived from flat index, coalesced.
//  * division elimination: one bs/A divide per thread; batch id via boundary
//    compare (A >> TPB).
//  * plain default-policy loads/stores. Measured neutral-or-worse: .cs hints,
//    __ldcs, TMA bulk stores, occ 54-94%, TPB 128-512, stream consolidation.
//  Kernel is pinned at the GB300 HBM mixed R/W ceiling for this 1:5 stream.

constexpr int TPB    = 128;       // 4 warps per block
constexpr int STAGE  = 32;        // t's staged per round
constexpr int ROUNDS = TPB / STAGE;
constexpr int ROW    = 52;        // padded smem row stride (48 data + 4 pad)

__global__ void __launch_bounds__(TPB)
box_decode_c8_kernel(const float* __restrict__ anchors,   // [A,4] cx,cy,w,h
                     const float* __restrict__ loc,       // [B,A,4]
                     const float* __restrict__ cls,       // [B,A,8]
                     const float* __restrict__ varx_p,
                     const float* __restrict__ vary_p,
                     const float* __restrict__ thr_p,
                     float* __restrict__ out_box,         // [B*A*8, 6]
                     float* __restrict__ out_mask,        // [B*A*8] or null
                     float* __restrict__ out_bidx,        // [B*A*8] or null
                     int A, long long total)              // total = B*A
{
    __shared__ float sm[STAGE * ROW];

    const long long bs = (long long)blockIdx.x * TPB;   // first t of this block
    const int tid = threadIdx.x;
    const long long t = bs + tid;

    const float varx = *varx_p;
    const float vary = *vary_p;
    const float thr  = *thr_p;

    // One divide per thread; batch id via boundary compare (A >> TPB).
    const int b0   = (int)(bs / A);
    const int rem0 = (int)(bs - (long long)b0 * A);     // anchor idx of t = bs

    // ---- decode own t into registers (long-pole loads issue early) ----
    float x0 = 0.f, y0 = 0.f, x1 = 0.f, y1 = 0.f;
    float s[8] = {0.f, 0.f, 0.f, 0.f, 0.f, 0.f, 0.f, 0.f};
    if (t < total) {
        int a = rem0 + tid;
        if (a >= A) a -= A;                         // at most one boundary per block

        float4 anc = __ldg((const float4*)anchors + a);   // cx,cy,w,h (L2-reused)
        float4 lp  = __ldg((const float4*)loc + t);

        float4 s01 = __ldg((const float4*)cls + t * 2);
        float4 s23 = __ldg((const float4*)cls + t * 2 + 1);

        float cx = lp.x * varx * anc.z + anc.x;
        float cy = lp.y * varx * anc.w + anc.y;
        float wd = __expf(lp.z * vary) * anc.z;
        float ht = __expf(lp.w * vary) * anc.w;

        x0 = cx - 0.5f * wd;
        y0 = cy - 0.5f * ht;
        x1 = cx + 0.5f * wd;
        y1 = cy + 0.5f * ht;

        s[0] = s01.x; s[1] = s01.y; s[2] = s01.z; s[3] = s01.w;
        s[4] = s23.x; s[5] = s23.y; s[6] = s23.z; s[7] = s23.w;

        // ---- mask fused: scores already in registers, no cls re-read ----
        if (out_mask) {
            ((float4*)out_mask)[t * 2] = make_float4(
                s[0] >= thr ? 1.0f : 0.0f,
                s[1] >= thr ? 1.0f : 0.0f,
                s[2] >= thr ? 1.0f : 0.0f,
                s[3] >= thr ? 1.0f : 0.0f);
            ((float4*)out_mask)[t * 2 + 1] = make_float4(
                s[4] >= thr ? 1.0f : 0.0f,
                s[5] >= thr ? 1.0f : 0.0f,
                s[6] >= thr ? 1.0f : 0.0f,
                s[7] >= thr ? 1.0f : 0.0f);
        }
    }

    // ---- batch_index: derived from index, coalesced ----
    if (out_bidx) {
#pragma unroll
        for (int k = 0; k < 2; k++) {
            long long j = bs * 2 + (long long)k * TPB + tid;  // float4 idx, t' = j>>1
            if (j < total * 2) {
                int off = rem0 + k * (TPB / 2) + (tid >> 1);  // t' - b0*A
                float bf = (float)(b0 + (off >= A ? 1 : 0));
                ((float4*)out_bidx)[j] = make_float4(bf, bf, bf, bf);
            }
        }
    }

    // ---- ROUNDS rounds: stage STAGE t's, flush coalesced ----
#pragma unroll
    for (int round = 0; round < ROUNDS; round++) {
        if ((tid >> 5) == round && t < total) {
            float4* row = (float4*)(sm + (tid & (STAGE - 1)) * ROW);
#pragma unroll
            for (int p = 0; p < 4; p++) {          // class pair (2p, 2p+1)
                row[3 * p + 0] = make_float4(x0, y0, x1, y1);
                row[3 * p + 1] = make_float4(s[2 * p], (float)(2 * p + 1), x0, y0);
                row[3 * p + 2] = make_float4(x1, y1, s[2 * p + 1], (float)(2 * p + 2));
            }
        }
        __syncthreads();

        const long long rbase = bs + (long long)round * STAGE;    // first t this round
        const int nvalid = (int)max(0LL, min((long long)STAGE, total - rbase));
        const int nf4 = nvalid * 12;
        float4* dst = (float4*)out_box + rbase * 12;
#pragma unroll
        for (int k = 0; k < 3; k++) {              // STAGE*12 / TPB = 3
            int i = tid + k * TPB;
            if (i < nf4) {
                int tl  = i / 12;                  // div by constant: mul+shift
                int pos = i - tl * 12;
                dst[i] = *(const float4*)(sm + tl * ROW + pos * 4);
            }
        }
        if (round != ROUNDS - 1) __syncthreads();  // protect buffer before reuse
    }
}

// Generic-C fallback (scalar stores), in case C != 8.
__global__ void __launch_bounds__(256)
box_decode_generic_kernel(const float* __restrict__ anchors,
                          const float* __restrict__ loc,
                          const float* __restrict__ cls,
                          const float* __restrict__ varx_p,
                          const float* __restrict__ vary_p,
                          const float* __restrict__ thr_p,
                          float* __restrict__ out_box,
                          float* __restrict__ out_mask,
                          float* __restrict__ out_bidx,
                          int A, int C, long long total)
{
    long long t = (long long)blockIdx.x * blockDim.x + threadIdx.x;
    if (t >= total) return;

    const float varx = *varx_p;
    const float vary = *vary_p;
    const float thr  = *thr_p;

    int b = (int)(t / A);
    int a = (int)(t - (long long)b * A);

    float4 anc = __ldg((const float4*)anchors + a);
    float4 lp  = __ldg((const float4*)loc + t);

    float cx = lp.x * varx * anc.z + anc.x;
    float cy = lp.y * varx * anc.w + anc.y;
    float w  = expf(lp.z * vary) * anc.z;
    float h  = expf(lp.w * vary) * anc.w;

    float x0 = cx - 0.5f * w;
    float y0 = cy - 0.5f * h;
    float x1 = cx + 0.5f * w;
    float y1 = cy + 0.5f * h;

    for (int c = 0; c < C; c++) {
        long long r = t * C + c;
        float sc = cls[r];
        float* row = out_box + r * 6;
        row[0] = x0; row[1] = y0; row[2] = x1; row[3] = y1;
        row[4] = sc; row[5] = (float)(c + 1);
        if (out_mask) out_mask[r] = (sc >= thr) ? 1.0f : 0.0f;
        if (out_bidx) out_bidx[r] = (float)b;
    }
}

extern "C" void kernel_launch(void* const* d_in, const int* in_sizes, int n_in,
                              void* d_out, int out_size)
{
    // Input order per setup_inputs: anchors, loc_preds, cls_preds,
    // varx, vary, score_thresh, batch_size
    const float* anchors = (const float*)d_in[0];
    const float* loc     = (const float*)d_in[1];
    const float* cls     = (const float*)d_in[2];
    const float* varx_p  = (const float*)d_in[3];
    const float* vary_p  = (const float*)d_in[4];
    const float* thr_p   = (const float*)d_in[5];

    const long long A   = in_sizes[0] / 4;
    const long long B   = in_sizes[1] / (A * 4);
    const long long C   = in_sizes[2] / (B * A);
    const long long BAC = B * A * C;
    const long long total = B * A;

    float* out = (float*)d_out;
    float* out_box  = out;                                        // BAC*6
    float* out_mask = (out_size >= (long long)(BAC * 7)) ? out + BAC * 6 : nullptr;
    float* out_bidx = (out_size >= (long long)(BAC * 8)) ? out + BAC * 7 : nullptr;

    // Hedge: if the harness allocated more than we write, clear the tail
    // (d_out is poisoned to 0xAA). Graph-capturable async memset.
    long long written = BAC * 6;
    if (out_mask) written = BAC * 7;
    if (out_bidx) written = BAC * 8;
    if ((long long)out_size > written) {
        cudaMemsetAsync(out + written, 0,
                        ((long long)out_size - written) * sizeof(float));
    }

    if (C == 8) {
        const long long blocks = (total + TPB - 1) / TPB;
        box_decode_c8_kernel<<<(unsigned)blocks, TPB>>>(
            anchors, loc, cls, varx_p, vary_p, thr_p,
            out_box, out_mask, out_bidx, (int)A, total);
    } else {
        const int threads = 256;
        const long long blocks = (total + threads - 1) / threads;
        box_decode_generic_kernel<<<(unsigned)blocks, threads>>>(
            anchors, loc, cls, varx_p, vary_p, thr_p,
            out_box, out_mask, out_bidx, (int)A, (int)C, total);
    }
}

// round 17
// speedup vs baseline: 1.2143x; 1.0206x over previous
#include <cuda_runtime.h>
#include <cuda_bf16.h>

// BoxDecoder: anchor decode + score-threshold mask.
// out layout (f32): [ box_tensor (B*A*C*6) | mask (B*A*C) | batch_index (B*A*C) ]
//
// R17 = R13 + warp-shuffle mask coalescing (R16 fixed: each warp owns 32 t's
// = 64 mask float4s, so each lane must write TWO f4s, not one — R16 wrote
// half the mask stream and failed correctness).
//  * mask compares packed to 8 bits; two __shfl_syncs redistribute them so
//    lanes write fully-coalesced float4s (R13's direct stores: 32B lane
//    stride -> 2x store wavefronts; R14's smem route cost more than saved).
//  * box: quarter-buffer block-phased staging, ROW=52 conflict-free STS.128,
//    flush 3 f4/thread/round, perfectly coalesced.
//  * no cls re-read; batch_index from flat index; division elimination.
//  * plain default-policy loads/stores (alternatives all measured worse).
//  Kernel pinned at GB300 HBM mixed R/W ceiling (~5.9 TB/s, ~74% DRAM).

constexpr int TPB    = 128;       // 4 warps per block
constexpr int STAGE  = 32;        // t's staged per round
constexpr int ROUNDS = TPB / STAGE;
constexpr int ROW    = 52;        // padded smem row stride (48 data + 4 pad)

__global__ void __launch_bounds__(TPB)
box_decode_c8_kernel(const float* __restrict__ anchors,   // [A,4] cx,cy,w,h
                     const float* __restrict__ loc,       // [B,A,4]
                     const float* __restrict__ cls,       // [B,A,8]
                     const float* __restrict__ varx_p,
                     const float* __restrict__ vary_p,
                     const float* __restrict__ thr_p,
                     float* __restrict__ out_box,         // [B*A*8, 6]
                     float* __restrict__ out_mask,        // [B*A*8] or null
                     float* __restrict__ out_bidx,        // [B*A*8] or null
                     int A, long long total)              // total = B*A
{
    __shared__ float sm[STAGE * ROW];

    const long long bs = (long long)blockIdx.x * TPB;   // first t of this block
    const int tid  = threadIdx.x;
    const int lane = tid & 31;
    const int w    = tid >> 5;
    const long long t = bs + tid;

    const float varx = *varx_p;
    const float vary = *vary_p;
    const float thr  = *thr_p;

    // One divide per thread; batch id via boundary compare (A >> TPB).
    const int b0   = (int)(bs / A);
    const int rem0 = (int)(bs - (long long)b0 * A);     // anchor idx of t = bs

    // ---- decode own t into registers (long-pole loads issue early) ----
    float x0 = 0.f, y0 = 0.f, x1 = 0.f, y1 = 0.f;
    float s[8] = {0.f, 0.f, 0.f, 0.f, 0.f, 0.f, 0.f, 0.f};
    unsigned mbits = 0;                             // 8 threshold compare bits
    if (t < total) {
        int a = rem0 + tid;
        if (a >= A) a -= A;                         // at most one boundary per block

        float4 anc = __ldg((const float4*)anchors + a);   // cx,cy,w,h (L2-reused)
        float4 lp  = __ldg((const float4*)loc + t);

        float4 s01 = __ldg((const float4*)cls + t * 2);
        float4 s23 = __ldg((const float4*)cls + t * 2 + 1);

        float cx = lp.x * varx * anc.z + anc.x;
        float cy = lp.y * varx * anc.w + anc.y;
        float wd = __expf(lp.z * vary) * anc.z;
        float ht = __expf(lp.w * vary) * anc.w;

        x0 = cx - 0.5f * wd;
        y0 = cy - 0.5f * ht;
        x1 = cx + 0.5f * wd;
        y1 = cy + 0.5f * ht;

        s[0] = s01.x; s[1] = s01.y; s[2] = s01.z; s[3] = s01.w;
        s[4] = s23.x; s[5] = s23.y; s[6] = s23.z; s[7] = s23.w;

#pragma unroll
        for (int c = 0; c < 8; c++)
            mbits |= (s[c] >= thr ? 1u : 0u) << c;
    }

    // ---- mask: warp-shuffle redistribution -> fully coalesced stores ----
    // Warp owns t's [warpbase, warpbase+32) = 64 mask float4s. For k=0,1:
    // lane writes f4 idx = k*32+lane (0..63); its 4 bits come from the lane
    // owning t' = warpbase + (idx>>1), nibble idx&1.
    if (out_mask) {
        const long long wbase2 = (bs + (long long)w * 32) * 2;   // first f4 of warp
#pragma unroll
        for (int k = 0; k < 2; k++) {
            int idx = k * 32 + lane;               // 0..63
            unsigned mb = __shfl_sync(0xffffffffu, mbits, idx >> 1);
            int sh = (idx & 1) * 4;
            long long j = wbase2 + idx;
            if (j < total * 2) {
                ((float4*)out_mask)[j] = make_float4(
                    (mb >> (sh + 0)) & 1 ? 1.0f : 0.0f,
                    (mb >> (sh + 1)) & 1 ? 1.0f : 0.0f,
                    (mb >> (sh + 2)) & 1 ? 1.0f : 0.0f,
                    (mb >> (sh + 3)) & 1 ? 1.0f : 0.0f);
            }
        }
    }

    // ---- batch_index: derived from index, coalesced ----
    if (out_bidx) {
#pragma unroll
        for (int k = 0; k < 2; k++) {
            long long j = bs * 2 + (long long)k * TPB + tid;  // float4 idx, t' = j>>1
            if (j < total * 2) {
                int off = rem0 + k * (TPB / 2) + (tid >> 1);  // t' - b0*A
                float bf = (float)(b0 + (off >= A ? 1 : 0));
                ((float4*)out_bidx)[j] = make_float4(bf, bf, bf, bf);
            }
        }
    }

    // ---- ROUNDS rounds: stage STAGE t's, flush coalesced ----
#pragma unroll
    for (int round = 0; round < ROUNDS; round++) {
        if (w == round && t < total) {
            float4* row = (float4*)(sm + lane * ROW);
#pragma unroll
            for (int p = 0; p < 4; p++) {          // class pair (2p, 2p+1)
                row[3 * p + 0] = make_float4(x0, y0, x1, y1);
                row[3 * p + 1] = make_float4(s[2 * p], (float)(2 * p + 1), x0, y0);
                row[3 * p + 2] = make_float4(x1, y1, s[2 * p + 1], (float)(2 * p + 2));
            }
        }
        __syncthreads();

        const long long rbase = bs + (long long)round * STAGE;    // first t this round
        const int nvalid = (int)max(0LL, min((long long)STAGE, total - rbase));
        const int nf4 = nvalid * 12;
        float4* dst = (float4*)out_box + rbase * 12;
#pragma unroll
        for (int k = 0; k < 3; k++) {              // STAGE*12 / TPB = 3
            int i = tid + k * TPB;
            if (i < nf4) {
                int tl  = i / 12;                  // div by constant: mul+shift
                int pos = i - tl * 12;
                dst[i] = *(const float4*)(sm + tl * ROW + pos * 4);
            }
        }
        if (round != ROUNDS - 1) __syncthreads();  // protect buffer before reuse
    }
}

// Generic-C fallback (scalar stores), in case C != 8.
__global__ void __launch_bounds__(256)
box_decode_generic_kernel(const float* __restrict__ anchors,
                          const float* __restrict__ loc,
                          const float* __restrict__ cls,
                          const float* __restrict__ varx_p,
                          const float* __restrict__ vary_p,
                          const float* __restrict__ thr_p,
                          float* __restrict__ out_box,
                          float* __restrict__ out_mask,
                          float* __restrict__ out_bidx,
                          int A, int C, long long total)
{
    long long t = (long long)blockIdx.x * blockDim.x + threadIdx.x;
    if (t >= total) return;

    const float varx = *varx_p;
    const float vary = *vary_p;
    const float thr  = *thr_p;

    int b = (int)(t / A);
    int a = (int)(t - (long long)b * A);

    float4 anc = __ldg((const float4*)anchors + a);
    float4 lp  = __ldg((const float4*)loc + t);

    float cx = lp.x * varx * anc.z + anc.x;
    float cy = lp.y * varx * anc.w + anc.y;
    float w  = expf(lp.z * vary) * anc.z;
    float h  = expf(lp.w * vary) * anc.w;

    float x0 = cx - 0.5f * w;
    float y0 = cy - 0.5f * h;
    float x1 = cx + 0.5f * w;
    float y1 = cy + 0.5f * h;

    for (int c = 0; c < C; c++) {
        long long r = t * C + c;
        float sc = cls[r];
        float* row = out_box + r * 6;
        row[0] = x0; row[1] = y0; row[2] = x1; row[3] = y1;
        row[4] = sc; row[5] = (float)(c + 1);
        if (out_mask) out_mask[r] = (sc >= thr) ? 1.0f : 0.0f;
        if (out_bidx) out_bidx[r] = (float)b;
    }
}

extern "C" void kernel_launch(void* const* d_in, const int* in_sizes, int n_in,
                              void* d_out, int out_size)
{
    // Input order per setup_inputs: anchors, loc_preds, cls_preds,
    // varx, vary, score_thresh, batch_size
    const float* anchors = (const float*)d_in[0];
    const float* loc     = (const float*)d_in[1];
    const float* cls     = (const float*)d_in[2];
    const float* varx_p  = (const float*)d_in[3];
    const float* vary_p  = (const float*)d_in[4];
    const float* thr_p   = (const float*)d_in[5];

    const long long A   = in_sizes[0] / 4;
    const long long B   = in_sizes[1] / (A * 4);
    const long long C   = in_sizes[2] / (B * A);
    const long long BAC = B * A * C;
    const long long total = B * A;

    float* out = (float*)d_out;
    float* out_box  = out;                                        // BAC*6
    float* out_mask = (out_size >= (long long)(BAC * 7)) ? out + BAC * 6 : nullptr;
    float* out_bidx = (out_size >= (long long)(BAC * 8)) ? out + BAC * 7 : nullptr;

    // Hedge: if the harness allocated more than we write, clear the tail
    // (d_out is poisoned to 0xAA). Graph-capturable async memset.
    long long written = BAC * 6;
    if (out_mask) written = BAC * 7;
    if (out_bidx) written = BAC * 8;
    if ((long long)out_size > written) {
        cudaMemsetAsync(out + written, 0,
                        ((long long)out_size - written) * sizeof(float));
    }

    if (C == 8) {
        const long long blocks = (total + TPB - 1) / TPB;
        box_decode_c8_kernel<<<(unsigned)blocks, TPB>>>(
            anchors, loc, cls, varx_p, vary_p, thr_p,
            out_box, out_mask, out_bidx, (int)A, total);
    } else {
        const int threads = 256;
        const long long blocks = (total + threads - 1) / threads;
        box_decode_generic_kernel<<<(unsigned)blocks, threads>>>(
            anchors, loc, cls, varx_p, vary_p, thr_p,
            out_box, out_mask, out_bidx, (int)A, (int)C, total);
    }
}